// round 2
// baseline (speedup 1.0000x reference)
#include <cuda_runtime.h>

#define L  4096   // tokens (64x64)
#define CH 256    // channels
#define NH 16     // heads (head_dim = 4)

// Scratch (allocation-free rule: __device__ globals). Each ulonglong2 = packed float4.
__device__ ulonglong2 g_q  [NH * L];  // normalized q, pre-scaled by log2(e)
__device__ ulonglong2 g_k  [NH * L];  // normalized k
__device__ ulonglong2 g_v  [NH * L];  // raw V
__device__ ulonglong2 g_vp [NH * L];  // V / Z_j
__device__ ulonglong2 g_att[NH * L];  // out[d, i] per head

// ---------- packed f32x2 helpers ----------
__device__ __forceinline__ unsigned long long ffma2(unsigned long long a,
                                                    unsigned long long b,
                                                    unsigned long long c) {
    unsigned long long d;
    asm("fma.rn.f32x2 %0, %1, %2, %3;" : "=l"(d) : "l"(a), "l"(b), "l"(c));
    return d;
}
__device__ __forceinline__ float2 unpk(unsigned long long v) {
    float2 f;
    asm("mov.b64 {%0, %1}, %2;" : "=f"(f.x), "=f"(f.y) : "l"(v));
    return f;
}
__device__ __forceinline__ unsigned long long pk(float x, float y) {
    unsigned long long v;
    asm("mov.b64 %0, {%1, %2};" : "=l"(v) : "f"(x), "f"(y));
    return v;
}
__device__ __forceinline__ float ex2a(float x) {
    float y;
    asm("ex2.approx.f32 %0, %1;" : "=f"(y) : "f"(x));
    return y;
}

// ---------- Kernel 1: QKV projection (1x1 conv) + L2 normalize ----------
// grid (16 l-tiles, 16 heads), block 256. Each thread owns one l, all 12 outputs
// (q0..3, k0..3, v0..3) of its head.
__global__ void qkv_kernel(const float* __restrict__ X,
                           const float* __restrict__ Wq, const float* __restrict__ bq,
                           const float* __restrict__ Wk, const float* __restrict__ bk,
                           const float* __restrict__ Wv, const float* __restrict__ bv) {
    __shared__ __align__(16) float wsm[CH][16];  // [c][r], r = 0..11 used
    const int tid = threadIdx.x;
    const int h   = blockIdx.y;
    const int l   = blockIdx.x * 256 + tid;

    // Stage the 12 weight rows for this head: wsm[c][r]
#pragma unroll
    for (int r = 0; r < 12; ++r) {
        const float* W = (r < 4) ? Wq : (r < 8) ? Wk : Wv;
        const int d = r & 3;
        wsm[tid][r] = W[(h * 4 + d) * CH + tid];
    }
    __syncthreads();

    float a[12];
#pragma unroll
    for (int r = 0; r < 12; ++r) a[r] = 0.0f;

#pragma unroll 4
    for (int c = 0; c < CH; ++c) {
        const float x = X[c * L + l];
        const float4* w = (const float4*)wsm[c];
        const float4 w0 = w[0], w1 = w[1], w2 = w[2];
        a[0]  = fmaf(w0.x, x, a[0]);  a[1]  = fmaf(w0.y, x, a[1]);
        a[2]  = fmaf(w0.z, x, a[2]);  a[3]  = fmaf(w0.w, x, a[3]);
        a[4]  = fmaf(w1.x, x, a[4]);  a[5]  = fmaf(w1.y, x, a[5]);
        a[6]  = fmaf(w1.z, x, a[6]);  a[7]  = fmaf(w1.w, x, a[7]);
        a[8]  = fmaf(w2.x, x, a[8]);  a[9]  = fmaf(w2.y, x, a[9]);
        a[10] = fmaf(w2.z, x, a[10]); a[11] = fmaf(w2.w, x, a[11]);
    }

    const int ob = h * 4;
    float q0 = a[0] + bq[ob], q1 = a[1] + bq[ob + 1], q2 = a[2] + bq[ob + 2], q3 = a[3] + bq[ob + 3];
    float k0 = a[4] + bk[ob], k1 = a[5] + bk[ob + 1], k2 = a[6] + bk[ob + 2], k3 = a[7] + bk[ob + 3];
    float v0 = a[8] + bv[ob], v1 = a[9] + bv[ob + 1], v2 = a[10] + bv[ob + 2], v3 = a[11] + bv[ob + 3];

    // F.normalize over head-dim, eps=1e-12; q additionally scaled by log2(e)
    const float nq = q0 * q0 + q1 * q1 + q2 * q2 + q3 * q3;
    const float iq = 1.4426950408889634f / fmaxf(sqrtf(nq), 1e-12f);
    q0 *= iq; q1 *= iq; q2 *= iq; q3 *= iq;
    const float nk = k0 * k0 + k1 * k1 + k2 * k2 + k3 * k3;
    const float ik = 1.0f / fmaxf(sqrtf(nk), 1e-12f);
    k0 *= ik; k1 *= ik; k2 *= ik; k3 *= ik;

    const int idx = h * L + l;
    g_q[idx] = make_ulonglong2(pk(q0, q1), pk(q2, q3));
    g_k[idx] = make_ulonglong2(pk(k0, k1), pk(k2, k3));
    g_v[idx] = make_ulonglong2(pk(v0, v1), pk(v2, v3));
}

// ---------- Kernel 2: Z-pass. Z_j = sum_i exp(q_j . k_i); g_vp = V / Z ----------
// grid (16 j-tiles, 16 heads), block 256; thread owns one j.
__global__ void zpass_kernel() {
    __shared__ ulonglong2 kb[256];
    const int tid = threadIdx.x;
    const int h   = blockIdx.y;
    const int j   = blockIdx.x * 256 + tid;

    const ulonglong2 qq = g_q[h * L + j];
    float z[4] = {0.f, 0.f, 0.f, 0.f};

    for (int ic = 0; ic < 16; ++ic) {
        __syncthreads();
        kb[tid] = g_k[h * L + ic * 256 + tid];
        __syncthreads();
#pragma unroll 8
        for (int m = 0; m < 256; ++m) {
            const ulonglong2 kk = kb[m];
            unsigned long long p = ffma2(qq.y, kk.y, ffma2(qq.x, kk.x, 0ULL));
            const float2 pf = unpk(p);
            z[m & 3] += ex2a(pf.x + pf.y);
        }
    }
    const float Z = (z[0] + z[1]) + (z[2] + z[3]);
    const float r = 1.0f / Z;
    const ulonglong2 vv = g_v[h * L + j];
    const float2 v01 = unpk(vv.x), v23 = unpk(vv.y);
    g_vp[h * L + j] = make_ulonglong2(pk(v01.x * r, v01.y * r),
                                      pk(v23.x * r, v23.y * r));
}

// ---------- Kernel 3: att-pass. out[d,i] = sum_j vp[d,j] * exp(q_j . k_i) ----------
// grid (16 i-tiles, 16 heads), block 256; thread owns one i.
__global__ void att_kernel() {
    __shared__ ulonglong2 qb[256];
    __shared__ ulonglong2 vb[256];
    const int tid = threadIdx.x;
    const int h   = blockIdx.y;
    const int i   = blockIdx.x * 256 + tid;

    const ulonglong2 kk = g_k[h * L + i];
    unsigned long long acc01 = 0ULL, acc23 = 0ULL;

    for (int jc = 0; jc < 16; ++jc) {
        __syncthreads();
        qb[tid] = g_q [h * L + jc * 256 + tid];
        vb[tid] = g_vp[h * L + jc * 256 + tid];
        __syncthreads();
#pragma unroll 4
        for (int m = 0; m < 256; ++m) {
            const ulonglong2 qq = qb[m];
            const ulonglong2 vv = vb[m];
            unsigned long long p = ffma2(qq.y, kk.y, ffma2(qq.x, kk.x, 0ULL));
            const float2 pf = unpk(p);
            const float e = ex2a(pf.x + pf.y);
            const unsigned long long ee = pk(e, e);
            acc01 = ffma2(vv.x, ee, acc01);
            acc23 = ffma2(vv.y, ee, acc23);
        }
    }
    g_att[h * L + i] = make_ulonglong2(acc01, acc23);
}

// ---------- Kernel 4: output projection + bias + residual ----------
// out[c,l] = X[c,l] + bo[c] + sum_o Wo[c,o] * att[o,l]
// grid (32 l-tiles of 128, 32 c-groups of 8), block 128.
__global__ void oproj_kernel(const float* __restrict__ X,
                             const float* __restrict__ Wo,
                             const float* __restrict__ bo,
                             float* __restrict__ out) {
    __shared__ __align__(16) float wsm[8][64];
    const int tid = threadIdx.x;
    const int cg  = blockIdx.y;
    const int l   = blockIdx.x * 128 + tid;

    for (int idx = tid; idx < 512; idx += 128) {
        const int cc = idx >> 6, o = idx & 63;
        wsm[cc][o] = Wo[(cg * 8 + cc) * 64 + o];
    }
    __syncthreads();

    unsigned long long acc[8];
#pragma unroll
    for (int cc = 0; cc < 8; ++cc) acc[cc] = 0ULL;

#pragma unroll
    for (int hh = 0; hh < NH; ++hh) {
        const ulonglong2 a = g_att[hh * L + l];
#pragma unroll
        for (int cc = 0; cc < 8; ++cc) {
            const ulonglong2 w = *(const ulonglong2*)&wsm[cc][hh * 4];
            acc[cc] = ffma2(a.x, w.x, acc[cc]);
            acc[cc] = ffma2(a.y, w.y, acc[cc]);
        }
    }
#pragma unroll
    for (int cc = 0; cc < 8; ++cc) {
        const int c = cg * 8 + cc;
        const float2 f = unpk(acc[cc]);
        out[c * L + l] = X[c * L + l] + bo[c] + f.x + f.y;
    }
}

extern "C" void kernel_launch(void* const* d_in, const int* in_sizes, int n_in,
                              void* d_out, int out_size) {
    (void)in_sizes; (void)n_in; (void)out_size;
    const float* X  = (const float*)d_in[0];
    const float* Wq = (const float*)d_in[1];
    const float* bq = (const float*)d_in[2];
    const float* Wk = (const float*)d_in[3];
    const float* bk = (const float*)d_in[4];
    const float* Wv = (const float*)d_in[5];
    const float* bv = (const float*)d_in[6];
    const float* Wo = (const float*)d_in[7];
    const float* bo = (const float*)d_in[8];
    float* out = (float*)d_out;

    qkv_kernel <<<dim3(16, 16), 256>>>(X, Wq, bq, Wk, bk, Wv, bv);
    zpass_kernel<<<dim3(16, 16), 256>>>();
    att_kernel <<<dim3(16, 16), 256>>>();
    oproj_kernel<<<dim3(32, 32), 128>>>(X, Wo, bo, out);
}

// round 3
// speedup vs baseline: 3.8774x; 3.8774x over previous
#include <cuda_runtime.h>

#define L  4096   // tokens (64x64)
#define CH 256    // channels
#define NH 16     // heads (head_dim = 4)
#define DEG 6
#define F  210    // monomials (a,b,c,d), a+b+c+d <= 6
#define NPAIR 28  // pairs (a,b), a+b <= 6

// Scratch (allocation-free rule: __device__ globals). ulonglong2 = packed float4.
__device__ ulonglong2 g_q  [NH * L];   // normalized q
__device__ ulonglong2 g_k  [NH * L];   // normalized k
__device__ ulonglong2 g_v  [NH * L];   // raw V
__device__ ulonglong2 g_vp [NH * L];   // V / Z_j
__device__ ulonglong2 g_att[NH * L];   // out[d, i] per head
__device__ float  g_S[NH * F];         // k-moments per head
__device__ float  g_M[NH * F * 4];     // [h][alpha][d] q,vp-moments
__device__ float  g_w[F];              // c_{|a|} * |a|!/alpha!
__device__ uchar2 g_pp[F];             // alpha -> (pair01 idx, pair23 idx)

// ---------- packed f32x2 helpers ----------
__device__ __forceinline__ unsigned long long ffma2(unsigned long long a,
                                                    unsigned long long b,
                                                    unsigned long long c) {
    unsigned long long d;
    asm("fma.rn.f32x2 %0, %1, %2, %3;" : "=l"(d) : "l"(a), "l"(b), "l"(c));
    return d;
}
__device__ __forceinline__ float2 unpk(unsigned long long v) {
    float2 f;
    asm("mov.b64 {%0, %1}, %2;" : "=f"(f.x), "=f"(f.y) : "l"(v));
    return f;
}
__device__ __forceinline__ unsigned long long pk(float x, float y) {
    unsigned long long v;
    asm("mov.b64 %0, {%1, %2};" : "=l"(v) : "f"(x), "f"(y));
    return v;
}

// ---------- Kernel 0: init tables + zero accumulators ----------
__global__ void init_kernel() {
    const int t = threadIdx.x;
    for (int i = t; i < NH * F; i += 256)     g_S[i] = 0.0f;
    for (int i = t; i < NH * F * 4; i += 256) g_M[i] = 0.0f;
    if (t < F) {
        // Chebyshev-truncated deg-6 coefficients of e^x on [-1,1] (max err ~3.4e-6)
        const float cc[7] = {0.9999998013203132f, 1.0000222899985483f,
                             0.5000063476462252f, 0.1664888731563763f,
                             0.04163501123055814f, 0.0086868209906231f,
                             0.0014392748707944755f};
        const float fact[7] = {1.f, 1.f, 2.f, 6.f, 24.f, 120.f, 720.f};
        int idx = 0;
        for (int a = 0; a <= DEG; ++a)
            for (int b = 0; b <= DEG - a; ++b)
                for (int c = 0; c <= DEG - a - b; ++c)
                    for (int d = 0; d <= DEG - a - b - c; ++d) {
                        if (idx == t) {
                            const int tt = a + b + c + d;
                            g_w[t] = cc[tt] * fact[tt] /
                                     (fact[a] * fact[b] * fact[c] * fact[d]);
                            const int p01 = a * 7 - (a * (a - 1)) / 2 + b;
                            const int p23 = c * 7 - (c * (c - 1)) / 2 + d;
                            g_pp[t] = make_uchar2((unsigned char)p01, (unsigned char)p23);
                        }
                        idx++;
                    }
    }
}

// ---------- Kernel 1: QKV projection (1x1 conv) + L2 normalize ----------
__global__ void qkv_kernel(const float* __restrict__ X,
                           const float* __restrict__ Wq, const float* __restrict__ bq,
                           const float* __restrict__ Wk, const float* __restrict__ bk,
                           const float* __restrict__ Wv, const float* __restrict__ bv) {
    __shared__ __align__(16) float wsm[CH][16];
    const int tid = threadIdx.x;
    const int h   = blockIdx.y;
    const int l   = blockIdx.x * 256 + tid;

#pragma unroll
    for (int r = 0; r < 12; ++r) {
        const float* W = (r < 4) ? Wq : (r < 8) ? Wk : Wv;
        wsm[tid][r] = W[(h * 4 + (r & 3)) * CH + tid];
    }
    __syncthreads();

    float a[12];
#pragma unroll
    for (int r = 0; r < 12; ++r) a[r] = 0.0f;

#pragma unroll 4
    for (int c = 0; c < CH; ++c) {
        const float x = X[c * L + l];
        const float4* w = (const float4*)wsm[c];
        const float4 w0 = w[0], w1 = w[1], w2 = w[2];
        a[0]  = fmaf(w0.x, x, a[0]);  a[1]  = fmaf(w0.y, x, a[1]);
        a[2]  = fmaf(w0.z, x, a[2]);  a[3]  = fmaf(w0.w, x, a[3]);
        a[4]  = fmaf(w1.x, x, a[4]);  a[5]  = fmaf(w1.y, x, a[5]);
        a[6]  = fmaf(w1.z, x, a[6]);  a[7]  = fmaf(w1.w, x, a[7]);
        a[8]  = fmaf(w2.x, x, a[8]);  a[9]  = fmaf(w2.y, x, a[9]);
        a[10] = fmaf(w2.z, x, a[10]); a[11] = fmaf(w2.w, x, a[11]);
    }

    const int ob = h * 4;
    float q0 = a[0] + bq[ob], q1 = a[1] + bq[ob + 1], q2 = a[2] + bq[ob + 2], q3 = a[3] + bq[ob + 3];
    float k0 = a[4] + bk[ob], k1 = a[5] + bk[ob + 1], k2 = a[6] + bk[ob + 2], k3 = a[7] + bk[ob + 3];
    float v0 = a[8] + bv[ob], v1 = a[9] + bv[ob + 1], v2 = a[10] + bv[ob + 2], v3 = a[11] + bv[ob + 3];

    const float nq = q0 * q0 + q1 * q1 + q2 * q2 + q3 * q3;
    const float iq = 1.0f / fmaxf(sqrtf(nq), 1e-12f);
    q0 *= iq; q1 *= iq; q2 *= iq; q3 *= iq;
    const float nk = k0 * k0 + k1 * k1 + k2 * k2 + k3 * k3;
    const float ik = 1.0f / fmaxf(sqrtf(nk), 1e-12f);
    k0 *= ik; k1 *= ik; k2 *= ik; k3 *= ik;

    const int idx = h * L + l;
    g_q[idx] = make_ulonglong2(pk(q0, q1), pk(q2, q3));
    g_k[idx] = make_ulonglong2(pk(k0, k1), pk(k2, k3));
    g_v[idx] = make_ulonglong2(pk(v0, v1), pk(v2, v3));
}

// ---------- shared helper: fill pairwise-product row for one token ----------
__device__ __forceinline__ void fill_pp_row(float* row, float x0, float x1,
                                            float x2, float x3) {
    float pw0[7], pw1[7], pw2[7], pw3[7];
    pw0[0] = pw1[0] = pw2[0] = pw3[0] = 1.0f;
#pragma unroll
    for (int p = 1; p <= DEG; ++p) {
        pw0[p] = pw0[p - 1] * x0; pw1[p] = pw1[p - 1] * x1;
        pw2[p] = pw2[p - 1] * x2; pw3[p] = pw3[p - 1] * x3;
    }
    int p = 0;
#pragma unroll
    for (int a = 0; a <= DEG; ++a)
#pragma unroll
        for (int b = 0; b <= DEG - a; ++b) row[p++] = pw0[a] * pw1[b];
    p = 0;
#pragma unroll
    for (int c = 0; c <= DEG; ++c)
#pragma unroll
        for (int d = 0; d <= DEG - c; ++d) row[NPAIR + p++] = pw2[c] * pw3[d];
}

// ---------- Kernel 2: k-moments. S_alpha[h] += sum_i k_i^alpha ----------
// grid (32 tiles of 128 i, 16 heads), block 256.
__global__ void kmom_kernel() {
    __shared__ float PP[128][2 * NPAIR + 1];   // 57 floats/row
    const int t = threadIdx.x;
    const int h = blockIdx.y;

    if (t < 128) {
        const ulonglong2 kk = g_k[h * L + blockIdx.x * 128 + t];
        const float2 k01 = unpk(kk.x), k23 = unpk(kk.y);
        fill_pp_row(PP[t], k01.x, k01.y, k23.x, k23.y);
    }
    __syncthreads();

    if (t < F) {
        const uchar2 pi = g_pp[t];
        const int px = pi.x, py = NPAIR + pi.y;
        float acc0 = 0.f, acc1 = 0.f;
#pragma unroll 4
        for (int i = 0; i < 128; i += 2) {
            acc0 += PP[i][px] * PP[i][py];
            acc1 += PP[i + 1][px] * PP[i + 1][py];
        }
        atomicAdd(&g_S[h * F + t], acc0 + acc1);
    }
}

// ---------- Kernel 3: Z per j (polynomial row-sum), vp = v / Z ----------
// grid (16 tiles of 256 j, 16 heads), block 256.
__global__ void zvp_kernel() {
    __shared__ float Ssh[F];
    const int t = threadIdx.x;
    const int h = blockIdx.y;
    const int j = blockIdx.x * 256 + t;

    if (t < F) Ssh[t] = g_w[t] * g_S[h * F + t];
    __syncthreads();

    const ulonglong2 qq = g_q[h * L + j];
    const float2 q01 = unpk(qq.x), q23 = unpk(qq.y);
    const float x0 = q01.x, x1 = q01.y, x2 = q23.x, x3 = q23.y;

    float accA = 0.f, accB = 0.f;
    int idx = 0;
    float pa = 1.0f;
#pragma unroll
    for (int a = 0; a <= DEG; ++a) {
        float pab = pa;
#pragma unroll
        for (int b = 0; b <= DEG - a; ++b) {
            float pabc = pab;
#pragma unroll
            for (int c = 0; c <= DEG - a - b; ++c) {
                float pabcd = pabc;
#pragma unroll
                for (int d = 0; d <= DEG - a - b - c; ++d) {
                    if (idx & 1) accB = fmaf(pabcd, Ssh[idx], accB);
                    else         accA = fmaf(pabcd, Ssh[idx], accA);
                    idx++;
                    pabcd *= x3;
                }
                pabc *= x2;
            }
            pab *= x1;
        }
        pa *= x0;
    }
    const float r = 1.0f / (accA + accB);
    const ulonglong2 vv = g_v[h * L + j];
    const float2 v01 = unpk(vv.x), v23 = unpk(vv.y);
    g_vp[h * L + j] = make_ulonglong2(pk(v01.x * r, v01.y * r),
                                      pk(v23.x * r, v23.y * r));
}

// ---------- Kernel 4: q,vp-moments. M[h][alpha][d] += sum_j vp_j[d] q_j^alpha ----------
// grid (32 tiles of 128 j, 16 heads), block 256.
__global__ void qmom_kernel() {
    __shared__ float PP[128][2 * NPAIR + 1];
    __shared__ ulonglong2 VPs[128];
    const int t = threadIdx.x;
    const int h = blockIdx.y;

    if (t < 128) {
        const int j = blockIdx.x * 128 + t;
        const ulonglong2 qq = g_q[h * L + j];
        const float2 q01 = unpk(qq.x), q23 = unpk(qq.y);
        fill_pp_row(PP[t], q01.x, q01.y, q23.x, q23.y);
        VPs[t] = g_vp[h * L + j];
    }
    __syncthreads();

    if (t < F) {
        const uchar2 pi = g_pp[t];
        const int px = pi.x, py = NPAIR + pi.y;
        unsigned long long a01A = 0ULL, a23A = 0ULL, a01B = 0ULL, a23B = 0ULL;
#pragma unroll 2
        for (int j = 0; j < 128; j += 2) {
            const float m0 = PP[j][px] * PP[j][py];
            const ulonglong2 v0 = VPs[j];
            const unsigned long long mm0 = pk(m0, m0);
            a01A = ffma2(v0.x, mm0, a01A);
            a23A = ffma2(v0.y, mm0, a23A);
            const float m1 = PP[j + 1][px] * PP[j + 1][py];
            const ulonglong2 v1 = VPs[j + 1];
            const unsigned long long mm1 = pk(m1, m1);
            a01B = ffma2(v1.x, mm1, a01B);
            a23B = ffma2(v1.y, mm1, a23B);
        }
        const float2 r01a = unpk(a01A), r01b = unpk(a01B);
        const float2 r23a = unpk(a23A), r23b = unpk(a23B);
        float* M = &g_M[(h * F + t) * 4];
        atomicAdd(&M[0], r01a.x + r01b.x);
        atomicAdd(&M[1], r01a.y + r01b.y);
        atomicAdd(&M[2], r23a.x + r23b.x);
        atomicAdd(&M[3], r23a.y + r23b.y);
    }
}

// ---------- Kernel 5: evaluate out[d,i] = sum_alpha w_a * M[d,alpha] * k_i^alpha ----------
// grid (16 tiles of 256 i, 16 heads), block 256.
__global__ void ceval_kernel() {
    __shared__ ulonglong2 Msh[F];
    const int t = threadIdx.x;
    const int h = blockIdx.y;
    const int i = blockIdx.x * 256 + t;

    if (t < F) {
        const float w = g_w[t];
        const float* m = &g_M[(h * F + t) * 4];
        Msh[t] = make_ulonglong2(pk(w * m[0], w * m[1]), pk(w * m[2], w * m[3]));
    }
    __syncthreads();

    const ulonglong2 kk = g_k[h * L + i];
    const float2 k01 = unpk(kk.x), k23 = unpk(kk.y);
    const float x0 = k01.x, x1 = k01.y, x2 = k23.x, x3 = k23.y;

    unsigned long long a01A = 0ULL, a23A = 0ULL, a01B = 0ULL, a23B = 0ULL;
    int idx = 0;
    float pa = 1.0f;
#pragma unroll
    for (int a = 0; a <= DEG; ++a) {
        float pab = pa;
#pragma unroll
        for (int b = 0; b <= DEG - a; ++b) {
            float pabc = pab;
#pragma unroll
            for (int c = 0; c <= DEG - a - b; ++c) {
                float pabcd = pabc;
#pragma unroll
                for (int d = 0; d <= DEG - a - b - c; ++d) {
                    const unsigned long long mm = pk(pabcd, pabcd);
                    const ulonglong2 M = Msh[idx];
                    if (idx & 1) {
                        a01B = ffma2(mm, M.x, a01B);
                        a23B = ffma2(mm, M.y, a23B);
                    } else {
                        a01A = ffma2(mm, M.x, a01A);
                        a23A = ffma2(mm, M.y, a23A);
                    }
                    idx++;
                    pabcd *= x3;
                }
                pabc *= x2;
            }
            pab *= x1;
        }
        pa *= x0;
    }
    const float2 r01a = unpk(a01A), r01b = unpk(a01B);
    const float2 r23a = unpk(a23A), r23b = unpk(a23B);
    g_att[h * L + i] = make_ulonglong2(pk(r01a.x + r01b.x, r01a.y + r01b.y),
                                       pk(r23a.x + r23b.x, r23a.y + r23b.y));
}

// ---------- Kernel 6: output projection + bias + residual ----------
// grid (32 l-tiles of 128, 16 c-groups of 16), block 128.
__global__ void oproj_kernel(const float* __restrict__ X,
                             const float* __restrict__ Wo,
                             const float* __restrict__ bo,
                             float* __restrict__ out) {
    __shared__ __align__(16) float wsm[16][64];
    const int tid = threadIdx.x;
    const int cg  = blockIdx.y;
    const int l   = blockIdx.x * 128 + tid;

    for (int idx = tid; idx < 16 * 64; idx += 128) {
        wsm[idx >> 6][idx & 63] = Wo[(cg * 16 + (idx >> 6)) * 64 + (idx & 63)];
    }
    __syncthreads();

    unsigned long long acc[16];
#pragma unroll
    for (int cc = 0; cc < 16; ++cc) acc[cc] = 0ULL;

#pragma unroll
    for (int hh = 0; hh < NH; ++hh) {
        const ulonglong2 a = g_att[hh * L + l];
#pragma unroll
        for (int cc = 0; cc < 16; ++cc) {
            const ulonglong2 w = *(const ulonglong2*)&wsm[cc][hh * 4];
            acc[cc] = ffma2(a.x, w.x, acc[cc]);
            acc[cc] = ffma2(a.y, w.y, acc[cc]);
        }
    }
#pragma unroll
    for (int cc = 0; cc < 16; ++cc) {
        const int c = cg * 16 + cc;
        const float2 f = unpk(acc[cc]);
        out[c * L + l] = X[c * L + l] + bo[c] + f.x + f.y;
    }
}

extern "C" void kernel_launch(void* const* d_in, const int* in_sizes, int n_in,
                              void* d_out, int out_size) {
    (void)in_sizes; (void)n_in; (void)out_size;
    const float* X  = (const float*)d_in[0];
    const float* Wq = (const float*)d_in[1];
    const float* bq = (const float*)d_in[2];
    const float* Wk = (const float*)d_in[3];
    const float* bk = (const float*)d_in[4];
    const float* Wv = (const float*)d_in[5];
    const float* bv = (const float*)d_in[6];
    const float* Wo = (const float*)d_in[7];
    const float* bo = (const float*)d_in[8];
    float* out = (float*)d_out;

    init_kernel <<<1, 256>>>();
    qkv_kernel  <<<dim3(16, 16), 256>>>(X, Wq, bq, Wk, bk, Wv, bv);
    kmom_kernel <<<dim3(32, 16), 256>>>();
    zvp_kernel  <<<dim3(16, 16), 256>>>();
    qmom_kernel <<<dim3(32, 16), 256>>>();
    ceval_kernel<<<dim3(16, 16), 256>>>();
    oproj_kernel<<<dim3(32, 16), 128>>>(X, Wo, bo, out);
}

// round 4
// speedup vs baseline: 4.6139x; 1.1899x over previous
#include <cuda_runtime.h>

#define L  4096   // tokens (64x64)
#define CH 256    // channels
#define NH 16     // heads (head_dim = 4)
#define DEG 6
#define F  210    // monomials (a,b,c,d), a+b+c+d <= 6
#define NPAIR 28  // pairs (a,b), a+b <= 6
#define PPW 58    // PP row stride (28 + 28 + pad)

// Scratch (allocation-free rule: __device__ globals).
__device__ ulonglong2 g_q  [NH * L];        // normalized q
__device__ ulonglong2 g_k  [NH * L];        // normalized k
__device__ ulonglong2 g_v  [NH * L];        // raw V
__device__ ulonglong2 g_att[NH * L];        // out[d, i] per head
__device__ float      g_Sp [NH * 16 * F];   // k-moment partials per block
__device__ float4     g_Mp [NH * 16 * F];   // q,vp-moment partials per block

// ---------- packed f32x2 helpers ----------
__device__ __forceinline__ unsigned long long ffma2(unsigned long long a,
                                                    unsigned long long b,
                                                    unsigned long long c) {
    unsigned long long d;
    asm("fma.rn.f32x2 %0, %1, %2, %3;" : "=l"(d) : "l"(a), "l"(b), "l"(c));
    return d;
}
__device__ __forceinline__ float2 unpk(unsigned long long v) {
    float2 f;
    asm("mov.b64 {%0, %1}, %2;" : "=f"(f.x), "=f"(f.y) : "l"(v));
    return f;
}
__device__ __forceinline__ unsigned long long pk(float x, float y) {
    unsigned long long v;
    asm("mov.b64 %0, {%1, %2};" : "=l"(v) : "f"(x), "f"(y));
    return v;
}

// ---------- monomial tables, computed inline (no init kernel) ----------
// Chebyshev-truncated deg-6 coefficients of e^x on [-1,1] (max err ~3.4e-6)
__device__ __forceinline__ void alpha_decode(int t, int& A, int& B, int& C, int& D) {
    int idx = 0;
    for (int a = 0; a <= DEG; ++a)
        for (int b = 0; b <= DEG - a; ++b)
            for (int c = 0; c <= DEG - a - b; ++c) {
                const int dmax = DEG - a - b - c;
                if (t - idx <= dmax) { A = a; B = b; C = c; D = t - idx; return; }
                idx += dmax + 1;
            }
    A = B = C = D = 0;
}
__device__ __forceinline__ void monomial_info(int t, float& w, int& px, int& py) {
    const float cc[7] = {0.9999998013203132f, 1.0000222899985483f,
                         0.5000063476462252f, 0.1664888731563763f,
                         0.04163501123055814f, 0.0086868209906231f,
                         0.0014392748707944755f};
    const float fact[7] = {1.f, 1.f, 2.f, 6.f, 24.f, 120.f, 720.f};
    int a, b, c, d;
    alpha_decode(t, a, b, c, d);
    const int s = a + b + c + d;
    w  = cc[s] * fact[s] / (fact[a] * fact[b] * fact[c] * fact[d]);
    px = a * 7 - (a * (a - 1)) / 2 + b;
    py = NPAIR + c * 7 - (c * (c - 1)) / 2 + d;
}

// ---------- fill pairwise-product row for one token ----------
__device__ __forceinline__ void fill_pp_row(float* row, float x0, float x1,
                                            float x2, float x3) {
    float pw0[7], pw1[7], pw2[7], pw3[7];
    pw0[0] = pw1[0] = pw2[0] = pw3[0] = 1.0f;
#pragma unroll
    for (int p = 1; p <= DEG; ++p) {
        pw0[p] = pw0[p - 1] * x0; pw1[p] = pw1[p - 1] * x1;
        pw2[p] = pw2[p - 1] * x2; pw3[p] = pw3[p - 1] * x3;
    }
    int p = 0;
#pragma unroll
    for (int a = 0; a <= DEG; ++a)
#pragma unroll
        for (int b = 0; b <= DEG - a; ++b) row[p++] = pw0[a] * pw1[b];
    p = NPAIR;
#pragma unroll
    for (int c = 0; c <= DEG; ++c)
#pragma unroll
        for (int d = 0; d <= DEG - c; ++d) row[p++] = pw2[c] * pw3[d];
}

// ============ Kernel 1: QKV projection (packed FFMA2) + normalize + k-moment partials ============
// grid (16 l-tiles of 256, 16 heads), block 256.
__global__ void qkv_kmom_kernel(const float* __restrict__ X,
                                const float* __restrict__ Wq, const float* __restrict__ bq,
                                const float* __restrict__ Wk, const float* __restrict__ bk,
                                const float* __restrict__ Wv, const float* __restrict__ bv) {
    __shared__ __align__(16) float sbuf[128 * PPW];   // union: wsm[256][12] then PP[128][58]
    __shared__ ulonglong2 karr[256];
    const int tid = threadIdx.x;
    const int h   = blockIdx.y;
    const int l   = blockIdx.x * 256 + tid;

    // stage weights: sbuf[c*12 + r], r = q0..3,k0..3,v0..3 (rows 16B-aligned: 48B stride)
#pragma unroll
    for (int r = 0; r < 12; ++r) {
        const float* W = (r < 4) ? Wq : (r < 8) ? Wk : Wv;
        sbuf[tid * 12 + r] = W[(h * 4 + (r & 3)) * CH + tid];
    }
    __syncthreads();

    unsigned long long acc[6];
#pragma unroll
    for (int r = 0; r < 6; ++r) acc[r] = 0ULL;

#pragma unroll 4
    for (int c = 0; c < CH; ++c) {
        const float x = X[c * L + l];
        const unsigned long long xx = pk(x, x);
        const ulonglong2* w = (const ulonglong2*)&sbuf[c * 12];
        const ulonglong2 wA = w[0], wB = w[1], wC = w[2];
        acc[0] = ffma2(wA.x, xx, acc[0]); acc[1] = ffma2(wA.y, xx, acc[1]);
        acc[2] = ffma2(wB.x, xx, acc[2]); acc[3] = ffma2(wB.y, xx, acc[3]);
        acc[4] = ffma2(wC.x, xx, acc[4]); acc[5] = ffma2(wC.y, xx, acc[5]);
    }

    const int ob = h * 4;
    float2 f;
    f = unpk(acc[0]); float q0 = f.x + bq[ob],     q1 = f.y + bq[ob + 1];
    f = unpk(acc[1]); float q2 = f.x + bq[ob + 2], q3 = f.y + bq[ob + 3];
    f = unpk(acc[2]); float k0 = f.x + bk[ob],     k1 = f.y + bk[ob + 1];
    f = unpk(acc[3]); float k2 = f.x + bk[ob + 2], k3 = f.y + bk[ob + 3];
    f = unpk(acc[4]); float v0 = f.x + bv[ob],     v1 = f.y + bv[ob + 1];
    f = unpk(acc[5]); float v2 = f.x + bv[ob + 2], v3 = f.y + bv[ob + 3];

    const float nq = q0 * q0 + q1 * q1 + q2 * q2 + q3 * q3;
    const float iq = 1.0f / fmaxf(sqrtf(nq), 1e-12f);
    q0 *= iq; q1 *= iq; q2 *= iq; q3 *= iq;
    const float nk = k0 * k0 + k1 * k1 + k2 * k2 + k3 * k3;
    const float ik = 1.0f / fmaxf(sqrtf(nk), 1e-12f);
    k0 *= ik; k1 *= ik; k2 *= ik; k3 *= ik;

    const int idx = h * L + l;
    g_q[idx] = make_ulonglong2(pk(q0, q1), pk(q2, q3));
    const ulonglong2 kk = make_ulonglong2(pk(k0, k1), pk(k2, k3));
    g_k[idx] = kk;
    g_v[idx] = make_ulonglong2(pk(v0, v1), pk(v2, v3));
    karr[tid] = kk;

    // --- k-moment partials over this block's 256 tokens (two 128-row tiles) ---
    int px = 0, py = 0; float wdummy;
    if (tid < F) monomial_info(tid, wdummy, px, py);

    float accS = 0.0f;
#pragma unroll
    for (int half = 0; half < 2; ++half) {
        __syncthreads();   // first iter: also fences wsm reads before PP overwrite
        if (tid < 128) {
            const ulonglong2 kr = karr[half * 128 + tid];
            const float2 k01 = unpk(kr.x), k23 = unpk(kr.y);
            fill_pp_row(&sbuf[tid * PPW], k01.x, k01.y, k23.x, k23.y);
        }
        __syncthreads();
        if (tid < F) {
            float s0 = 0.f, s1 = 0.f;
#pragma unroll 4
            for (int i = 0; i < 128; i += 2) {
                s0 += sbuf[i * PPW + px] * sbuf[i * PPW + py];
                s1 += sbuf[(i + 1) * PPW + px] * sbuf[(i + 1) * PPW + py];
            }
            accS += s0 + s1;
        }
    }
    if (tid < F) g_Sp[(h * 16 + blockIdx.x) * F + tid] = accS;
}

// ============ Kernel 2: Z per j, vp = v/Z, q/vp-moment partials (fused) ============
// grid (16 j-tiles of 256, 16 heads), block 256.
__global__ void zvp_qmom_kernel() {
    __shared__ float Ssh[F];
    __shared__ ulonglong2 qarr[256];
    __shared__ ulonglong2 VPs[256];
    __shared__ __align__(16) float PPb[128 * PPW];
    const int tid = threadIdx.x;
    const int h   = blockIdx.y;
    const int j   = blockIdx.x * 256 + tid;

    int px = 0, py = 0;
    if (tid < F) {
        float w;
        monomial_info(tid, w, px, py);
        float s = 0.0f;
#pragma unroll
        for (int b = 0; b < 16; ++b) s += g_Sp[(h * 16 + b) * F + tid];
        Ssh[tid] = w * s;
    }
    const ulonglong2 qq = g_q[h * L + j];
    qarr[tid] = qq;
    __syncthreads();

    const float2 q01 = unpk(qq.x), q23 = unpk(qq.y);
    const float x0 = q01.x, x1 = q01.y, x2 = q23.x, x3 = q23.y;

    // Z_j = sum_alpha w_a S_a q_j^alpha
    float accA = 0.f, accB = 0.f;
    {
        int idx = 0;
        float pa = 1.0f;
#pragma unroll
        for (int a = 0; a <= DEG; ++a) {
            float pab = pa;
#pragma unroll
            for (int b = 0; b <= DEG - a; ++b) {
                float pabc = pab;
#pragma unroll
                for (int c = 0; c <= DEG - a - b; ++c) {
                    float pabcd = pabc;
#pragma unroll
                    for (int d = 0; d <= DEG - a - b - c; ++d) {
                        if (idx & 1) accB = fmaf(pabcd, Ssh[idx], accB);
                        else         accA = fmaf(pabcd, Ssh[idx], accA);
                        idx++;
                        pabcd *= x3;
                    }
                    pabc *= x2;
                }
                pab *= x1;
            }
            pa *= x0;
        }
    }
    const float r = 1.0f / (accA + accB);
    const ulonglong2 vv = g_v[h * L + j];
    const float2 v01 = unpk(vv.x), v23 = unpk(vv.y);
    VPs[tid] = make_ulonglong2(pk(v01.x * r, v01.y * r), pk(v23.x * r, v23.y * r));

    // --- moment partials: M[alpha][d] = sum_j vp_j[d] * q_j^alpha ---
    unsigned long long a01 = 0ULL, a23 = 0ULL;
#pragma unroll
    for (int half = 0; half < 2; ++half) {
        __syncthreads();
        if (tid < 128) {
            const ulonglong2 qr = qarr[half * 128 + tid];
            const float2 a2 = unpk(qr.x), b2 = unpk(qr.y);
            fill_pp_row(&PPb[tid * PPW], a2.x, a2.y, b2.x, b2.y);
        }
        __syncthreads();
        if (tid < F) {
#pragma unroll 2
            for (int i = 0; i < 128; ++i) {
                const float m = PPb[i * PPW + px] * PPb[i * PPW + py];
                const unsigned long long mm = pk(m, m);
                const ulonglong2 vp = VPs[half * 128 + i];
                a01 = ffma2(vp.x, mm, a01);
                a23 = ffma2(vp.y, mm, a23);
            }
        }
    }
    if (tid < F) {
        const float2 r01 = unpk(a01), r23 = unpk(a23);
        g_Mp[(h * 16 + blockIdx.x) * F + tid] = make_float4(r01.x, r01.y, r23.x, r23.y);
    }
}

// ============ Kernel 3: out[d,i] = sum_alpha w_a M[d,alpha] k_i^alpha ============
// grid (32 i-tiles of 128, 16 heads), block 128.
__global__ void ceval_kernel() {
    __shared__ ulonglong2 Msh[F];
    const int t = threadIdx.x;
    const int h = blockIdx.y;
    const int i = blockIdx.x * 128 + t;

    for (int tt = t; tt < F; tt += 128) {
        float w; int px, py;
        monomial_info(tt, w, px, py);
        float4 s = make_float4(0.f, 0.f, 0.f, 0.f);
#pragma unroll
        for (int b = 0; b < 16; ++b) {
            const float4 p = g_Mp[(h * 16 + b) * F + tt];
            s.x += p.x; s.y += p.y; s.z += p.z; s.w += p.w;
        }
        Msh[tt] = make_ulonglong2(pk(w * s.x, w * s.y), pk(w * s.z, w * s.w));
    }
    __syncthreads();

    const ulonglong2 kk = g_k[h * L + i];
    const float2 k01 = unpk(kk.x), k23 = unpk(kk.y);
    const float x0 = k01.x, x1 = k01.y, x2 = k23.x, x3 = k23.y;

    unsigned long long a01A = 0ULL, a23A = 0ULL, a01B = 0ULL, a23B = 0ULL;
    int idx = 0;
    float pa = 1.0f;
#pragma unroll
    for (int a = 0; a <= DEG; ++a) {
        float pab = pa;
#pragma unroll
        for (int b = 0; b <= DEG - a; ++b) {
            float pabc = pab;
#pragma unroll
            for (int c = 0; c <= DEG - a - b; ++c) {
                float pabcd = pabc;
#pragma unroll
                for (int d = 0; d <= DEG - a - b - c; ++d) {
                    const unsigned long long mm = pk(pabcd, pabcd);
                    const ulonglong2 M = Msh[idx];
                    if (idx & 1) {
                        a01B = ffma2(mm, M.x, a01B);
                        a23B = ffma2(mm, M.y, a23B);
                    } else {
                        a01A = ffma2(mm, M.x, a01A);
                        a23A = ffma2(mm, M.y, a23A);
                    }
                    idx++;
                    pabcd *= x3;
                }
                pabc *= x2;
            }
            pab *= x1;
        }
        pa *= x0;
    }
    const float2 r01a = unpk(a01A), r01b = unpk(a01B);
    const float2 r23a = unpk(a23A), r23b = unpk(a23B);
    g_att[h * L + i] = make_ulonglong2(pk(r01a.x + r01b.x, r01a.y + r01b.y),
                                       pk(r23a.x + r23b.x, r23a.y + r23b.y));
}

// ============ Kernel 4: output projection + bias + residual ============
// grid (32 l-tiles of 128, 16 c-groups of 16), block 128.
__global__ void oproj_kernel(const float* __restrict__ X,
                             const float* __restrict__ Wo,
                             const float* __restrict__ bo,
                             float* __restrict__ out) {
    __shared__ __align__(16) float wsm[16][64];
    const int tid = threadIdx.x;
    const int cg  = blockIdx.y;
    const int l   = blockIdx.x * 128 + tid;

    for (int idx = tid; idx < 16 * 64; idx += 128) {
        wsm[idx >> 6][idx & 63] = Wo[(cg * 16 + (idx >> 6)) * 64 + (idx & 63)];
    }
    __syncthreads();

    unsigned long long acc[16];
#pragma unroll
    for (int cc = 0; cc < 16; ++cc) acc[cc] = 0ULL;

#pragma unroll
    for (int hh = 0; hh < NH; ++hh) {
        const ulonglong2 a = g_att[hh * L + l];
#pragma unroll
        for (int cc = 0; cc < 16; ++cc) {
            const ulonglong2 w = *(const ulonglong2*)&wsm[cc][hh * 4];
            acc[cc] = ffma2(a.x, w.x, acc[cc]);
            acc[cc] = ffma2(a.y, w.y, acc[cc]);
        }
    }
#pragma unroll
    for (int cc = 0; cc < 16; ++cc) {
        const int c = cg * 16 + cc;
        const float2 f = unpk(acc[cc]);
        out[c * L + l] = X[c * L + l] + bo[c] + f.x + f.y;
    }
}

extern "C" void kernel_launch(void* const* d_in, const int* in_sizes, int n_in,
                              void* d_out, int out_size) {
    (void)in_sizes; (void)n_in; (void)out_size;
    const float* X  = (const float*)d_in[0];
    const float* Wq = (const float*)d_in[1];
    const float* bq = (const float*)d_in[2];
    const float* Wk = (const float*)d_in[3];
    const float* bk = (const float*)d_in[4];
    const float* Wv = (const float*)d_in[5];
    const float* bv = (const float*)d_in[6];
    const float* Wo = (const float*)d_in[7];
    const float* bo = (const float*)d_in[8];
    float* out = (float*)d_out;

    qkv_kmom_kernel<<<dim3(16, 16), 256>>>(X, Wq, bq, Wk, bk, Wv, bv);
    zvp_qmom_kernel<<<dim3(16, 16), 256>>>();
    ceval_kernel   <<<dim3(32, 16), 128>>>();
    oproj_kernel   <<<dim3(32, 16), 128>>>(X, Wo, bo, out);
}